// round 14
// baseline (speedup 1.0000x reference)
#include <cuda_runtime.h>
#include <cuda_bf16.h>

#define N_NODES 8192
#define F_IN    256
#define F_OUT   128
#define CAPW    96    // per-warp segment capacity (mean ~10.4 edges/warp, sd 3.2)

// Scratch (no cudaMalloc allowed)
__device__ float g_xprime[N_NODES * F_OUT];
__device__ float g_ssrc[N_NODES];
__device__ float g_sdst[N_NODES];

// ---------------------------------------------------------------------------
// K1: x' = input @ weight + bias, fused s_src = x'·phi_src, s_dst = x'·phi_dst
// ---------------------------------------------------------------------------
__global__ __launch_bounds__(512) void gemm_score_kernel(
    const float* __restrict__ input,
    const float* __restrict__ weight,
    const float* __restrict__ bias,
    const float* __restrict__ phi)
{
    __shared__ float inpT[32][68];
    __shared__ float wsh[32][128];

    const int tx = threadIdx.x & 31;
    const int ty = threadIdx.x >> 5;
    const int r0 = blockIdx.x * 64;

    float acc[4][4];
    #pragma unroll
    for (int r = 0; r < 4; r++)
        #pragma unroll
        for (int c = 0; c < 4; c++) acc[r][c] = 0.f;

    for (int k0 = 0; k0 < F_IN; k0 += 32) {
        #pragma unroll
        for (int i = 0; i < 4; i++) {
            int e  = threadIdx.x + i * 512;
            int r  = e >> 5;
            int kk = e & 31;
            inpT[kk][r] = input[(size_t)(r0 + r) * F_IN + k0 + kk];
        }
        #pragma unroll
        for (int i = 0; i < 8; i++) {
            int e  = threadIdx.x + i * 512;
            int kk = e >> 7;
            int f  = e & 127;
            wsh[kk][f] = weight[(size_t)(k0 + kk) * F_OUT + f];
        }
        __syncthreads();

        #pragma unroll
        for (int kk = 0; kk < 32; kk++) {
            float4 b = *(const float4*)&wsh[kk][tx * 4];
            float4 a = *(const float4*)&inpT[kk][ty * 4];
            float av[4] = {a.x, a.y, a.z, a.w};
            #pragma unroll
            for (int r = 0; r < 4; r++) {
                acc[r][0] = fmaf(av[r], b.x, acc[r][0]);
                acc[r][1] = fmaf(av[r], b.y, acc[r][1]);
                acc[r][2] = fmaf(av[r], b.z, acc[r][2]);
                acc[r][3] = fmaf(av[r], b.w, acc[r][3]);
            }
        }
        __syncthreads();
    }

    float4 bi = *(const float4*)&bias[tx * 4];
    float4 ps = *(const float4*)&phi[tx * 4];
    float4 pd = *(const float4*)&phi[F_OUT + tx * 4];

    #pragma unroll
    for (int r = 0; r < 4; r++) {
        float4 v;
        v.x = acc[r][0] + bi.x;
        v.y = acc[r][1] + bi.y;
        v.z = acc[r][2] + bi.z;
        v.w = acc[r][3] + bi.w;
        int row = r0 + ty * 4 + r;
        *(float4*)&g_xprime[(size_t)row * F_OUT + tx * 4] = v;

        float psum = v.x * ps.x + v.y * ps.y + v.z * ps.z + v.w * ps.w;
        float dsum = v.x * pd.x + v.y * pd.y + v.z * pd.z + v.w * pd.w;
        #pragma unroll
        for (int o = 16; o; o >>= 1) {
            psum += __shfl_xor_sync(0xffffffffu, psum, o);
            dsum += __shfl_xor_sync(0xffffffffu, dsum, o);
        }
        if (tx == 0) {
            g_ssrc[row] = psum;
            g_sdst[row] = dsum;
        }
    }
}

// ---------------------------------------------------------------------------
// K2: block-per-row. Lane-local 32-bit occupancy mask (each lane owns 32
// adjacency entries; adj is exactly 0.0f/1.0f so bit 29 <=> edge). ONE warp
// prefix scan per row, divergent extraction (mean 0.32 edge/lane). No
// max-shift (exp(S) in fp32 range; the shift cancels in the division).
// Edge list stored interleaved as float2 {j-bits, e}: one STS.64 / LDS.64
// per edge. ONE __syncthreads per row. 6 blocks/SM for latency hiding.
// exp(-1e9) underflows to exactly 0 => sparse == dense reference.
// ---------------------------------------------------------------------------
__global__ __launch_bounds__(256, 6) void attn_kernel(
    const float* __restrict__ adj,      // [N, N]
    float* __restrict__ out)            // [N, F_OUT]
{
    __shared__ float2 nb[8 * CAPW];     // {.x = __int_as_float(j), .y = e}
    __shared__ float  zpart[8];
    __shared__ float  hpart[8][F_OUT];

    const int tid  = threadIdx.x;
    const int lane = tid & 31;
    const int wid  = tid >> 5;
    const int row  = blockIdx.x;

    const float si = __ldg(&g_ssrc[row]);
    const int segbase = wid * CAPW;

    // self-loop (mask = adj + I always includes the diagonal) -> warp 0 slot 0
    float zw = 0.f;
    int segn = (wid == 0) ? 1 : 0;
    if (tid == 0) {
        float S = si + g_sdst[row];
        S = (S >= 0.f) ? S : 0.2f * S;
        float e = __expf(S);
        nb[0] = make_float2(__int_as_float(row), e);
        zw = e;
    }

    // ---- Phase A: build lane-local 32-bit occupancy mask ----
    // Lane owns uint4 q = u*256 + tid (u=0..7) -> entries j = u*1024 + tid*4 + c
    // Bit b = u*4 + c.
    const uint4* arow = (const uint4*)(adj + (size_t)row * N_NODES);
    unsigned m32 = 0u;
    #pragma unroll
    for (int half = 0; half < 2; half++) {
        uint4 v[4];
        #pragma unroll
        for (int u = 0; u < 4; u++)
            v[u] = __ldcs(arow + (half * 4 + u) * 256 + tid);
        #pragma unroll
        for (int u = 0; u < 4; u++) {
            const int k = (half * 4 + u) * 4;
            // (word >> 29) & 1  ==  edge bit (1.0f = 0x3F800000)
            m32 |= ((v[u].x >> 29) & 1u) << k;
            m32 |= ((v[u].y >> 29) & 1u) << (k + 1);
            m32 |= ((v[u].z >> 29) & 1u) << (k + 2);
            m32 |= ((v[u].w >> 29) & 1u) << (k + 3);
        }
    }
    // drop the diagonal bit (self handled above): owner tid = (row>>2) & 255
    if (tid == ((row >> 2) & 255))
        m32 &= ~(1u << (((row >> 10) << 2) | (row & 3)));

    // ---- single warp prefix scan of popc ----
    int cnt = __popc(m32);
    int inc = cnt;
    #pragma unroll
    for (int o = 1; o < 32; o <<= 1) {
        int t = __shfl_up_sync(0xffffffffu, inc, o);
        if (lane >= o) inc += t;
    }
    int p = segbase + segn + (inc - cnt);          // exclusive offset
    segn += __shfl_sync(0xffffffffu, inc, 31);     // warp total

    // ---- extraction: mean 0.32 edges/lane, SIMT depth = max lane cnt (~2) ----
    const int jlane = tid << 2;
    while (m32) {
        int b = __ffs(m32) - 1;
        m32 &= m32 - 1;
        int j = ((b >> 2) << 10) + jlane + (b & 3);
        float S = si + __ldg(&g_sdst[j]);
        S = (S >= 0.f) ? S : 0.2f * S;             // leaky relu, slope 0.2
        float e = __expf(S);                       // no max shift needed
        nb[p] = make_float2(__int_as_float(j), e);
        p++;
        zw += e;
    }
    __syncwarp();   // warp-private segment visible to all lanes of this warp

    // ---- Phase B: warp-local gather, unroll 4 (MLP=4), 32-bit addressing ----
    float4 acc = make_float4(0.f, 0.f, 0.f, 0.f);
    const float* xpl = g_xprime + (lane << 2);
    int q = 0;
    for (; q + 4 <= segn; q += 4) {
        float2 n0 = nb[segbase + q],     n1 = nb[segbase + q + 1];
        float2 n2 = nb[segbase + q + 2], n3 = nb[segbase + q + 3];
        float4 x0 = *(const float4*)&xpl[__float_as_int(n0.x) << 7];
        float4 x1 = *(const float4*)&xpl[__float_as_int(n1.x) << 7];
        float4 x2 = *(const float4*)&xpl[__float_as_int(n2.x) << 7];
        float4 x3 = *(const float4*)&xpl[__float_as_int(n3.x) << 7];
        acc.x = fmaf(n0.y, x0.x, fmaf(n1.y, x1.x, fmaf(n2.y, x2.x, fmaf(n3.y, x3.x, acc.x))));
        acc.y = fmaf(n0.y, x0.y, fmaf(n1.y, x1.y, fmaf(n2.y, x2.y, fmaf(n3.y, x3.y, acc.y))));
        acc.z = fmaf(n0.y, x0.z, fmaf(n1.y, x1.z, fmaf(n2.y, x2.z, fmaf(n3.y, x3.z, acc.z))));
        acc.w = fmaf(n0.y, x0.w, fmaf(n1.y, x1.w, fmaf(n2.y, x2.w, fmaf(n3.y, x3.w, acc.w))));
    }
    for (; q < segn; q++) {
        float2 n0 = nb[segbase + q];
        float4 x0 = *(const float4*)&xpl[__float_as_int(n0.x) << 7];
        acc.x = fmaf(n0.y, x0.x, acc.x);
        acc.y = fmaf(n0.y, x0.y, acc.y);
        acc.z = fmaf(n0.y, x0.z, acc.z);
        acc.w = fmaf(n0.y, x0.w, acc.w);
    }

    // warp Z reduce + publish partials
    #pragma unroll
    for (int o = 16; o; o >>= 1) zw += __shfl_xor_sync(0xffffffffu, zw, o);
    *(float4*)&hpart[wid][lane << 2] = acc;
    if (lane == 0) zpart[wid] = zw;
    __syncthreads();                       // the ONLY block barrier

    // ---- final combine: 128 threads, one feature each ----
    if (tid < F_OUT) {
        float Z = zpart[0];
        #pragma unroll
        for (int w = 1; w < 8; w++) Z += zpart[w];
        float s = hpart[0][tid];
        #pragma unroll
        for (int w = 1; w < 8; w++) s += hpart[w][tid];
        out[(size_t)row * F_OUT + tid] = s / Z;
    }
}

extern "C" void kernel_launch(void* const* d_in, const int* in_sizes, int n_in,
                              void* d_out, int out_size) {
    const float* adj    = (const float*)d_in[0];
    const float* input  = (const float*)d_in[1];
    const float* weight = (const float*)d_in[2];
    const float* bias   = (const float*)d_in[3];
    const float* phi    = (const float*)d_in[4];
    float* out = (float*)d_out;

    gemm_score_kernel<<<N_NODES / 64, 512>>>(input, weight, bias, phi);
    attn_kernel<<<N_NODES, 256>>>(adj, out);
}

// round 16
// speedup vs baseline: 1.0032x; 1.0032x over previous
#include <cuda_runtime.h>
#include <cuda_bf16.h>
#include <mma.h>

using namespace nvcuda;

#define N_NODES 8192
#define F_IN    256
#define F_OUT   128
#define CAPW    96    // per-warp segment capacity (mean ~10.4 edges/warp, sd 3.2)

#define BM 64         // GEMM M-tile per block
#define BK 32         // GEMM K-chunk

// Scratch (no cudaMalloc allowed)
__device__ float g_xprime[N_NODES * F_OUT];
__device__ float g_ssrc[N_NODES];
__device__ float g_sdst[N_NODES];

// ---------------------------------------------------------------------------
// K1: x'' = input @ weight via 3xTF32 tensor-core GEMM (fp32-accurate).
// Split each operand a = hi + lo (hi = tf32(a), lo = tf32(a - hi)); compute
// hi*hi + hi*lo + lo*hi — dropped lo*lo term is O(2^-22) relative.
// Block: 256 thr = 8 warps in a 4(m) x 2(n) grid; warp tile 16 x 64.
// ---------------------------------------------------------------------------
__global__ __launch_bounds__(256) void gemm_tc_kernel(
    const float* __restrict__ input,    // [N, F_IN]
    const float* __restrict__ weight)   // [F_IN, F_OUT]
{
    __shared__ float As[BM][BK + 8];        // 64 x 40
    __shared__ float Ws[BK][F_OUT + 4];     // 32 x 132

    const int wid = threadIdx.x >> 5;
    const int wm  = wid >> 1;               // 0..3 -> m offset 16*wm
    const int wn  = wid & 1;                // 0..1 -> n offset 64*wn
    const int r0  = blockIdx.x * BM;

    wmma::fragment<wmma::accumulator, 16, 16, 8, float> c[4];
    #pragma unroll
    for (int nf = 0; nf < 4; nf++) wmma::fill_fragment(c[nf], 0.f);

    for (int k0 = 0; k0 < F_IN; k0 += BK) {
        // stage A tile (64 x 32) : 512 float4, 2 per thread
        #pragma unroll
        for (int i = threadIdx.x; i < BM * BK / 4; i += 256) {
            int r = i >> 3, cc = (i & 7) << 2;     // BK/4 = 8
            *(float4*)&As[r][cc] = *(const float4*)&input[(size_t)(r0 + r) * F_IN + k0 + cc];
        }
        // stage W tile (32 x 128) : 1024 float4, 4 per thread
        #pragma unroll
        for (int i = threadIdx.x; i < BK * F_OUT / 4; i += 256) {
            int r = i >> 5, cc = (i & 31) << 2;    // F_OUT/4 = 32
            *(float4*)&Ws[r][cc] = *(const float4*)&weight[(size_t)(k0 + r) * F_OUT + cc];
        }
        __syncthreads();

        #pragma unroll
        for (int ks = 0; ks < BK; ks += 8) {
            wmma::fragment<wmma::matrix_a, 16, 16, 8, wmma::precision::tf32, wmma::row_major> a_hi, a_lo;
            wmma::load_matrix_sync(a_hi, &As[wm * 16][ks], BK + 8);
            #pragma unroll
            for (int t = 0; t < a_hi.num_elements; t++) {
                float v  = a_hi.x[t];
                float hi = wmma::__float_to_tf32(v);
                a_lo.x[t] = wmma::__float_to_tf32(v - hi);
                a_hi.x[t] = hi;
            }
            #pragma unroll
            for (int nf = 0; nf < 4; nf++) {
                wmma::fragment<wmma::matrix_b, 16, 16, 8, wmma::precision::tf32, wmma::row_major> b_hi, b_lo;
                wmma::load_matrix_sync(b_hi, &Ws[ks][wn * 64 + nf * 16], F_OUT + 4);
                #pragma unroll
                for (int t = 0; t < b_hi.num_elements; t++) {
                    float v  = b_hi.x[t];
                    float hi = wmma::__float_to_tf32(v);
                    b_lo.x[t] = wmma::__float_to_tf32(v - hi);
                    b_hi.x[t] = hi;
                }
                wmma::mma_sync(c[nf], a_hi, b_hi, c[nf]);
                wmma::mma_sync(c[nf], a_lo, b_hi, c[nf]);
                wmma::mma_sync(c[nf], a_hi, b_lo, c[nf]);
            }
        }
        __syncthreads();
    }

    #pragma unroll
    for (int nf = 0; nf < 4; nf++)
        wmma::store_matrix_sync(
            &g_xprime[(size_t)(r0 + wm * 16) * F_OUT + wn * 64 + nf * 16],
            c[nf], F_OUT, wmma::mem_row_major);
}

// ---------------------------------------------------------------------------
// K1b: add bias in place + fused score dots. One warp per row.
// ---------------------------------------------------------------------------
__global__ __launch_bounds__(256) void score_kernel(
    const float* __restrict__ bias,     // [F_OUT]
    const float* __restrict__ phi)      // [2*F_OUT]
{
    const int lane = threadIdx.x & 31;
    const int row  = (blockIdx.x << 3) + (threadIdx.x >> 5);

    float4 bi = *(const float4*)&bias[lane * 4];
    float4 ps = *(const float4*)&phi[lane * 4];
    float4 pd = *(const float4*)&phi[F_OUT + lane * 4];

    float4 v = *(const float4*)&g_xprime[(size_t)row * F_OUT + lane * 4];
    v.x += bi.x; v.y += bi.y; v.z += bi.z; v.w += bi.w;
    *(float4*)&g_xprime[(size_t)row * F_OUT + lane * 4] = v;

    float psum = v.x * ps.x + v.y * ps.y + v.z * ps.z + v.w * ps.w;
    float dsum = v.x * pd.x + v.y * pd.y + v.z * pd.z + v.w * pd.w;
    #pragma unroll
    for (int o = 16; o; o >>= 1) {
        psum += __shfl_xor_sync(0xffffffffu, psum, o);
        dsum += __shfl_xor_sync(0xffffffffu, dsum, o);
    }
    if (lane == 0) {
        g_ssrc[row] = psum;
        g_sdst[row] = dsum;
    }
}

// ---------------------------------------------------------------------------
// K2 (exact R13 best config): block-per-row. Lane-local 32-bit occupancy mask
// (adj is exactly 0.0f/1.0f so bit 29 <=> edge). ONE warp prefix scan per row,
// divergent extraction (mean 0.32 edge/lane). No max-shift (exp(S) in fp32
// range; the shift cancels in the division). ONE __syncthreads per row.
// exp(-1e9) underflows to exactly 0 => sparse == dense reference.
// ---------------------------------------------------------------------------
__global__ __launch_bounds__(256, 5) void attn_kernel(
    const float* __restrict__ adj,      // [N, N]
    float* __restrict__ out)            // [N, F_OUT]
{
    __shared__ int   nb_j[8 * CAPW];
    __shared__ float nb_e[8 * CAPW];
    __shared__ float zpart[8];
    __shared__ float hpart[8][F_OUT];

    const int tid  = threadIdx.x;
    const int lane = tid & 31;
    const int wid  = tid >> 5;
    const int row  = blockIdx.x;

    const float si = g_ssrc[row];
    const int segbase = wid * CAPW;

    // self-loop (mask = adj + I always includes the diagonal) -> warp 0 slot 0
    float zw = 0.f;
    int segn = (wid == 0) ? 1 : 0;
    if (tid == 0) {
        float S = si + g_sdst[row];
        S = (S >= 0.f) ? S : 0.2f * S;
        float e = __expf(S);
        nb_j[0] = row;
        nb_e[0] = e;
        zw = e;
    }

    // ---- Phase A: build lane-local 32-bit occupancy mask ----
    const uint4* arow = (const uint4*)(adj + (size_t)row * N_NODES);
    unsigned m32 = 0u;
    #pragma unroll
    for (int half = 0; half < 2; half++) {
        uint4 v[4];
        #pragma unroll
        for (int u = 0; u < 4; u++)
            v[u] = __ldcs(arow + (half * 4 + u) * 256 + tid);
        #pragma unroll
        for (int u = 0; u < 4; u++) {
            const int k = (half * 4 + u) * 4;
            m32 |= ((v[u].x >> 29) & 1u) << k;
            m32 |= ((v[u].y >> 29) & 1u) << (k + 1);
            m32 |= ((v[u].z >> 29) & 1u) << (k + 2);
            m32 |= ((v[u].w >> 29) & 1u) << (k + 3);
        }
    }
    // drop the diagonal bit (self handled above): owner tid = (row>>2) & 255
    if (tid == ((row >> 2) & 255))
        m32 &= ~(1u << (((row >> 10) << 2) | (row & 3)));

    // ---- single warp prefix scan of popc ----
    int cnt = __popc(m32);
    int inc = cnt;
    #pragma unroll
    for (int o = 1; o < 32; o <<= 1) {
        int t = __shfl_up_sync(0xffffffffu, inc, o);
        if (lane >= o) inc += t;
    }
    int p = segbase + segn + (inc - cnt);          // exclusive offset
    segn += __shfl_sync(0xffffffffu, inc, 31);     // warp total

    // ---- extraction: mean 0.32 edges/lane ----
    const int jlane = tid << 2;
    while (m32) {
        int b = __ffs(m32) - 1;
        m32 &= m32 - 1;
        int j = ((b >> 2) << 10) + jlane + (b & 3);
        float S = si + __ldg(&g_sdst[j]);
        S = (S >= 0.f) ? S : 0.2f * S;             // leaky relu, slope 0.2
        float e = __expf(S);                       // no max shift needed
        nb_j[p] = j;
        nb_e[p] = e;
        p++;
        zw += e;
    }
    __syncwarp();

    // ---- Phase B: warp-local gather, unroll 4 (MLP=4), 32-bit addressing ----
    float4 acc = make_float4(0.f, 0.f, 0.f, 0.f);
    const float* xpl = g_xprime + (lane << 2);
    int q = 0;
    for (; q + 4 <= segn; q += 4) {
        int   j0 = nb_j[segbase + q],     j1 = nb_j[segbase + q + 1];
        int   j2 = nb_j[segbase + q + 2], j3 = nb_j[segbase + q + 3];
        float e0 = nb_e[segbase + q],     e1 = nb_e[segbase + q + 1];
        float e2 = nb_e[segbase + q + 2], e3 = nb_e[segbase + q + 3];
        float4 x0 = *(const float4*)&xpl[j0 << 7];
        float4 x1 = *(const float4*)&xpl[j1 << 7];
        float4 x2 = *(const float4*)&xpl[j2 << 7];
        float4 x3 = *(const float4*)&xpl[j3 << 7];
        acc.x = fmaf(e0, x0.x, fmaf(e1, x1.x, fmaf(e2, x2.x, fmaf(e3, x3.x, acc.x))));
        acc.y = fmaf(e0, x0.y, fmaf(e1, x1.y, fmaf(e2, x2.y, fmaf(e3, x3.y, acc.y))));
        acc.z = fmaf(e0, x0.z, fmaf(e1, x1.z, fmaf(e2, x2.z, fmaf(e3, x3.z, acc.z))));
        acc.w = fmaf(e0, x0.w, fmaf(e1, x1.w, fmaf(e2, x2.w, fmaf(e3, x3.w, acc.w))));
    }
    for (; q < segn; q++) {
        int   j0 = nb_j[segbase + q];
        float e0 = nb_e[segbase + q];
        float4 x0 = *(const float4*)&xpl[j0 << 7];
        acc.x = fmaf(e0, x0.x, acc.x);
        acc.y = fmaf(e0, x0.y, acc.y);
        acc.z = fmaf(e0, x0.z, acc.z);
        acc.w = fmaf(e0, x0.w, acc.w);
    }

    // warp Z reduce + publish partials
    #pragma unroll
    for (int o = 16; o; o >>= 1) zw += __shfl_xor_sync(0xffffffffu, zw, o);
    *(float4*)&hpart[wid][lane << 2] = acc;
    if (lane == 0) zpart[wid] = zw;
    __syncthreads();                       // the ONLY block barrier

    // ---- final combine: 128 threads, one feature each ----
    if (tid < F_OUT) {
        float Z = zpart[0];
        #pragma unroll
        for (int w = 1; w < 8; w++) Z += zpart[w];
        float s = hpart[0][tid];
        #pragma unroll
        for (int w = 1; w < 8; w++) s += hpart[w][tid];
        out[(size_t)row * F_OUT + tid] = s / Z;
    }
}

extern "C" void kernel_launch(void* const* d_in, const int* in_sizes, int n_in,
                              void* d_out, int out_size) {
    const float* adj    = (const float*)d_in[0];
    const float* input  = (const float*)d_in[1];
    const float* weight = (const float*)d_in[2];
    const float* bias   = (const float*)d_in[3];
    const float* phi    = (const float*)d_in[4];
    float* out = (float*)d_out;

    gemm_tc_kernel<<<N_NODES / BM, 256>>>(input, weight);
    score_kernel<<<N_NODES / 8, 256>>>(bias, phi);
    attn_kernel<<<N_NODES, 256>>>(adj, out);
}